// round 3
// baseline (speedup 1.0000x reference)
#include <cuda_runtime.h>
#include <cuda_fp16.h>
#include <cstdint>

// Problem constants
#define VOCAB 131072
#define EMB   128
#define HID   256
#define OUT_N 128
#define BATCH 256
#define SEQ_T 512

// Scratch (device globals; no allocations allowed)
__device__ float g_pre[(size_t)SEQ_T * BATCH * HID];   // [T][B][HID] fp32, includes b_ih+b_hh
__device__ float g_hT[BATCH * HID];                    // final hidden state fp32
__device__ int   g_x_is64;                             // 1 if x buffer is int64, else 0

// ---------------------------------------------------------------------------
// mma.sync m16n8k16 row.col f32.f16.f16.f32
// ---------------------------------------------------------------------------
__device__ __forceinline__ void mma16816(float c[4],
                                         unsigned a0, unsigned a1, unsigned a2, unsigned a3,
                                         unsigned b0, unsigned b1) {
    asm volatile(
        "mma.sync.aligned.m16n8k16.row.col.f32.f16.f16.f32 "
        "{%0,%1,%2,%3}, {%4,%5,%6,%7}, {%8,%9}, {%0,%1,%2,%3};\n"
        : "+f"(c[0]), "+f"(c[1]), "+f"(c[2]), "+f"(c[3])
        : "r"(a0), "r"(a1), "r"(a2), "r"(a3), "r"(b0), "r"(b1));
}

__device__ __forceinline__ float tanh_fast(float x) {
    // 1 - 2/(e^{2x}+1); MUFU EX2 + MUFU RCP, ~1e-6 accuracy, saturates correctly
    float e = __expf(2.0f * x);
    return 1.0f - __fdividef(2.0f, e + 1.0f);
}

__device__ __forceinline__ unsigned pack_half2(float a, float b) {
    __half2 h = __floats2half2_rn(a, b);
    return *reinterpret_cast<unsigned*>(&h);
}

// ---------------------------------------------------------------------------
// Kernel 0: detect whether x is int64 or int32 — reading ONLY the first
// 131072 32-bit words, which exist under either dtype (int32: whole buffer;
// int64: first half). If int64-LE, odd words (high halves) are all zero
// since indices < 2^17. If int32, odd words are uniform indices; P(all 65536
// of them are zero) ~ (1/VOCAB)^65536 ~ 0.
// ---------------------------------------------------------------------------
__global__ void k_detect_x64(const unsigned* __restrict__ xw) {
    __shared__ int s_any;
    if (threadIdx.x == 0) s_any = 0;
    __syncthreads();
    unsigned acc = 0;
    // odd word indices 1..131071 -> 65536 words, all within first 131072 words
    for (int i = threadIdx.x; i < (BATCH * SEQ_T) / 2; i += 256)
        acc |= xw[2 * i + 1];
    if (acc) atomicOr(&s_any, 1);
    __syncthreads();
    if (threadIdx.x == 0) g_x_is64 = (s_any == 0) ? 1 : 0;
}

__device__ __forceinline__ int load_index(const unsigned* xw, int pos) {
    // int64: value at word 2*pos (high word known zero); int32: at word pos.
    return (int)(g_x_is64 ? xw[2 * pos] : xw[pos]);
}

// ---------------------------------------------------------------------------
// Kernel 1: pre[t][b][:] = emb[x[b,t]] @ W_ih^T + (b_ih + b_hh)
// Gathered GEMM, M = B*T tokens tiled by 128, N=256, K=128. fp16 HMMA, fp32 out.
// grid: 256 blocks x 4 tiles each; block: 256 threads (8 warps: 2M x 4N)
// ---------------------------------------------------------------------------
#define K1_ASTRIDE 136   // halves per row (128 + 8 pad) -> conflict-free
#define K1_SMEM_BYTES ((128 * K1_ASTRIDE + 256 * K1_ASTRIDE) * 2 + 256 * 4)

__global__ __launch_bounds__(256, 1) void k_pre(const unsigned* __restrict__ xw,
                                                const float* __restrict__ emb,
                                                const float* __restrict__ W_ih,
                                                const float* __restrict__ b_ih,
                                                const float* __restrict__ b_hh) {
    extern __shared__ char smem[];
    __half (*Asm)[K1_ASTRIDE] = reinterpret_cast<__half(*)[K1_ASTRIDE]>(smem);
    __half (*Bsm)[K1_ASTRIDE] = reinterpret_cast<__half(*)[K1_ASTRIDE]>(smem + 128 * K1_ASTRIDE * 2);
    float* bias = reinterpret_cast<float*>(smem + (128 + 256) * K1_ASTRIDE * 2);

    const int tid  = threadIdx.x;
    const int wid  = tid >> 5;
    const int lane = tid & 31;
    const int r    = lane >> 2;
    const int cq   = lane & 3;
    const int wm   = wid & 1;   // 2 warps along M (64 rows each)
    const int wn   = wid >> 1;  // 4 warps along N (64 cols each)

    // bias = b_ih + b_hh
    bias[tid] = b_ih[tid] + b_hh[tid];

    // W_ih [256][128] fp32 -> Bsm fp16 (row-major [n][k])
    for (int i = tid; i < 256 * 128 / 4; i += 256) {
        int n  = i >> 5;          // 32 float4 per row
        int k4 = i & 31;
        float4 v = reinterpret_cast<const float4*>(W_ih)[i];
        __half2* dst = reinterpret_cast<__half2*>(&Bsm[n][k4 * 4]);
        dst[0] = __floats2half2_rn(v.x, v.y);
        dst[1] = __floats2half2_rn(v.z, v.w);
    }

    for (int it = 0; it < 4; it++) {
        const int i0 = (blockIdx.x * 4 + it) * 128;  // first token of tile
        __syncthreads();  // previous tile's mma reads done before overwrite

        // gather A: 128 tokens, 2 threads per token (64 floats each)
        {
            int tok = tid >> 1, hf = tid & 1;
            int gi = i0 + tok;
            int t = gi >> 8;          // token index = t*256 + b
            int b = gi & 255;
            int idx = load_index(xw, b * SEQ_T + t);
            const float4* src = reinterpret_cast<const float4*>(emb + (size_t)idx * EMB + hf * 64);
            __half2* dst = reinterpret_cast<__half2*>(&Asm[tok][hf * 64]);
#pragma unroll
            for (int q = 0; q < 16; q++) {
                float4 v = src[q];
                dst[q * 2 + 0] = __floats2half2_rn(v.x, v.y);
                dst[q * 2 + 1] = __floats2half2_rn(v.z, v.w);
            }
        }
        __syncthreads();

        float c[4][8][4];
#pragma unroll
        for (int mt = 0; mt < 4; mt++)
#pragma unroll
            for (int nt = 0; nt < 8; nt++)
#pragma unroll
                for (int q = 0; q < 4; q++) c[mt][nt][q] = 0.0f;

#pragma unroll
        for (int kt = 0; kt < 8; kt++) {
            unsigned a[4][4];
#pragma unroll
            for (int mt = 0; mt < 4; mt++) {
                int row = wm * 64 + mt * 16;
                int k0 = kt * 16 + 2 * cq;
                a[mt][0] = *reinterpret_cast<const unsigned*>(&Asm[row + r][k0]);
                a[mt][1] = *reinterpret_cast<const unsigned*>(&Asm[row + r + 8][k0]);
                a[mt][2] = *reinterpret_cast<const unsigned*>(&Asm[row + r][k0 + 8]);
                a[mt][3] = *reinterpret_cast<const unsigned*>(&Asm[row + r + 8][k0 + 8]);
            }
#pragma unroll
            for (int nt = 0; nt < 8; nt++) {
                int n = wn * 64 + nt * 8 + r;
                int k0 = kt * 16 + 2 * cq;
                unsigned b0 = *reinterpret_cast<const unsigned*>(&Bsm[n][k0]);
                unsigned b1 = *reinterpret_cast<const unsigned*>(&Bsm[n][k0 + 8]);
#pragma unroll
                for (int mt = 0; mt < 4; mt++) mma16816(c[mt][nt], a[mt][0], a[mt][1], a[mt][2], a[mt][3], b0, b1);
            }
        }

        // epilogue: add bias, store fp32 [token][256]
#pragma unroll
        for (int mt = 0; mt < 4; mt++) {
#pragma unroll
            for (int nt = 0; nt < 8; nt++) {
                int row = i0 + wm * 64 + mt * 16 + r;
                int col = wn * 64 + nt * 8 + 2 * cq;
                float bx = bias[col], by = bias[col + 1];
                float2 v0 = make_float2(c[mt][nt][0] + bx, c[mt][nt][1] + by);
                float2 v1 = make_float2(c[mt][nt][2] + bx, c[mt][nt][3] + by);
                *reinterpret_cast<float2*>(&g_pre[(size_t)row * HID + col]) = v0;
                *reinterpret_cast<float2*>(&g_pre[(size_t)(row + 8) * HID + col]) = v1;
            }
        }
    }
}

// ---------------------------------------------------------------------------
// Kernel 2: RNN recurrence. 16 CTAs, each owns 16 batch rows for all 512 steps.
// W_hh fp16 in smem, B-fragments register-resident (never re-read),
// h double-buffered fp16 in smem. 256 threads = 8 warps, each warp N=32.
// ---------------------------------------------------------------------------
#define K2_WSTRIDE 264  // 256 + 8 pad halves
#define K2_SMEM_BYTES ((256 * K2_WSTRIDE + 32 * K2_WSTRIDE) * 2)

__global__ __launch_bounds__(256, 1) void k_rnn(const float* __restrict__ W_hh) {
    extern __shared__ char smem[];
    __half (*Wsm)[K2_WSTRIDE] = reinterpret_cast<__half(*)[K2_WSTRIDE]>(smem);
    __half (*Hbuf)[K2_WSTRIDE] = reinterpret_cast<__half(*)[K2_WSTRIDE]>(smem + 256 * K2_WSTRIDE * 2); // 32 rows

    const int tid  = threadIdx.x;
    const int wid  = tid >> 5;
    const int lane = tid & 31;
    const int r    = lane >> 2;
    const int cq   = lane & 3;
    const int wn   = wid * 32;           // warp's N offset
    const int bRow0 = blockIdx.x * 16;   // this CTA's batch rows

    // W_hh [256][256] fp32 -> Wsm fp16 [n][k]
    for (int i = tid; i < 256 * 256 / 4; i += 256) {
        int n  = i >> 6;  // 64 float4 per row
        int k4 = i & 63;
        float4 v = reinterpret_cast<const float4*>(W_hh)[i];
        __half2* dst = reinterpret_cast<__half2*>(&Wsm[n][k4 * 4]);
        dst[0] = __floats2half2_rn(v.x, v.y);
        dst[1] = __floats2half2_rn(v.z, v.w);
    }
    // zero h buffers (h0 = 0)
    for (int i = tid; i < 32 * K2_WSTRIDE; i += 256)
        reinterpret_cast<__half*>(Hbuf)[i] = __ushort_as_half(0);
    __syncthreads();

    // preload register-resident B fragments: 16 k-tiles x 4 n-tiles x 2 regs
    unsigned bfr[16][4][2];
#pragma unroll
    for (int kt = 0; kt < 16; kt++)
#pragma unroll
        for (int nt = 0; nt < 4; nt++) {
            int n = wn + nt * 8 + r;
            int k0 = kt * 16 + 2 * cq;
            bfr[kt][nt][0] = *reinterpret_cast<const unsigned*>(&Wsm[n][k0]);
            bfr[kt][nt][1] = *reinterpret_cast<const unsigned*>(&Wsm[n][k0 + 8]);
        }

    int cur = 0;
    for (int t = 0; t < SEQ_T; t++) {
        // prefetch this step's pre (latency hidden by the mma phase below)
        const float* pt = g_pre + ((size_t)t * BATCH + bRow0) * HID;
        float2 pr[4][2];
#pragma unroll
        for (int nt = 0; nt < 4; nt++) {
            int col = wn + nt * 8 + 2 * cq;
            pr[nt][0] = *reinterpret_cast<const float2*>(pt + (size_t)r * HID + col);
            pr[nt][1] = *reinterpret_cast<const float2*>(pt + (size_t)(r + 8) * HID + col);
        }

        float c[4][4];
#pragma unroll
        for (int nt = 0; nt < 4; nt++)
#pragma unroll
            for (int q = 0; q < 4; q++) c[nt][q] = 0.0f;

        __half (*hc)[K2_WSTRIDE] = Hbuf + cur * 16;
#pragma unroll
        for (int kt = 0; kt < 16; kt++) {
            int k0 = kt * 16 + 2 * cq;
            unsigned a0 = *reinterpret_cast<const unsigned*>(&hc[r][k0]);
            unsigned a1 = *reinterpret_cast<const unsigned*>(&hc[r + 8][k0]);
            unsigned a2 = *reinterpret_cast<const unsigned*>(&hc[r][k0 + 8]);
            unsigned a3 = *reinterpret_cast<const unsigned*>(&hc[r + 8][k0 + 8]);
#pragma unroll
            for (int nt = 0; nt < 4; nt++)
                mma16816(c[nt], a0, a1, a2, a3, bfr[kt][nt][0], bfr[kt][nt][1]);
        }

        // epilogue: h_new = tanh(c + pre), write fp16 into the other buffer
        __half (*hn)[K2_WSTRIDE] = Hbuf + (cur ^ 1) * 16;
#pragma unroll
        for (int nt = 0; nt < 4; nt++) {
            int col = wn + nt * 8 + 2 * cq;
            float y0 = tanh_fast(c[nt][0] + pr[nt][0].x);
            float y1 = tanh_fast(c[nt][1] + pr[nt][0].y);
            float y2 = tanh_fast(c[nt][2] + pr[nt][1].x);
            float y3 = tanh_fast(c[nt][3] + pr[nt][1].y);
            *reinterpret_cast<unsigned*>(&hn[r][col]) = pack_half2(y0, y1);
            *reinterpret_cast<unsigned*>(&hn[r + 8][col]) = pack_half2(y2, y3);
            if (t == SEQ_T - 1) {
                *reinterpret_cast<float2*>(&g_hT[(size_t)(bRow0 + r) * HID + col]) = make_float2(y0, y1);
                *reinterpret_cast<float2*>(&g_hT[(size_t)(bRow0 + r + 8) * HID + col]) = make_float2(y2, y3);
            }
        }
        cur ^= 1;
        __syncthreads();
    }
}

// ---------------------------------------------------------------------------
// Kernel 3: y = hT @ Wp^T + bp, then layernorm over OUT=128.
// grid 256 (one block per batch row), 128 threads (one per output)
// ---------------------------------------------------------------------------
__global__ __launch_bounds__(128) void k_head(const float* __restrict__ Wp,
                                              const float* __restrict__ bp,
                                              const float* __restrict__ gamma,
                                              const float* __restrict__ beta,
                                              float* __restrict__ out) {
    const int b = blockIdx.x;
    const int o = threadIdx.x;
    const int lane = o & 31, wid = o >> 5;

    const float* h = g_hT + (size_t)b * HID;
    const float* w = Wp + (size_t)o * HID;
    float s = 0.0f;
#pragma unroll 8
    for (int k = 0; k < HID; k += 4) {
        float4 hv = *reinterpret_cast<const float4*>(h + k);
        float4 wv = *reinterpret_cast<const float4*>(w + k);
        s += hv.x * wv.x + hv.y * wv.y + hv.z * wv.z + hv.w * wv.w;
    }
    float y = s + bp[o];

    // block reduce sum(y), sum(y^2) across 128 threads
    float s1 = y, s2 = y * y;
#pragma unroll
    for (int off = 16; off > 0; off >>= 1) {
        s1 += __shfl_down_sync(0xffffffffu, s1, off);
        s2 += __shfl_down_sync(0xffffffffu, s2, off);
    }
    __shared__ float r1[4], r2[4];
    if (lane == 0) { r1[wid] = s1; r2[wid] = s2; }
    __syncthreads();
    float S1 = r1[0] + r1[1] + r1[2] + r1[3];
    float S2 = r2[0] + r2[1] + r2[2] + r2[3];
    float mu = S1 * (1.0f / OUT_N);
    float var = S2 * (1.0f / OUT_N) - mu * mu;
    float inv = rsqrtf(var + 1e-5f);
    out[(size_t)b * OUT_N + o] = (y - mu) * inv * gamma[o] + beta[o];
}

// ---------------------------------------------------------------------------
extern "C" void kernel_launch(void* const* d_in, const int* in_sizes, int n_in,
                              void* d_out, int out_size) {
    const unsigned* xw  = (const unsigned*)d_in[0];
    const float* emb   = (const float*)d_in[1];
    const float* W_ih  = (const float*)d_in[2];
    const float* W_hh  = (const float*)d_in[3];
    const float* b_ih  = (const float*)d_in[4];
    const float* b_hh  = (const float*)d_in[5];
    const float* Wp    = (const float*)d_in[6];
    const float* bp    = (const float*)d_in[7];
    const float* gamma = (const float*)d_in[8];
    const float* beta  = (const float*)d_in[9];
    float* out = (float*)d_out;

    cudaFuncSetAttribute(k_pre, cudaFuncAttributeMaxDynamicSharedMemorySize, K1_SMEM_BYTES);
    cudaFuncSetAttribute(k_rnn, cudaFuncAttributeMaxDynamicSharedMemorySize, K2_SMEM_BYTES);

    k_detect_x64<<<1, 256>>>(xw);
    k_pre<<<256, 256, K1_SMEM_BYTES>>>(xw, emb, W_ih, b_ih, b_hh);
    k_rnn<<<16, 256, K2_SMEM_BYTES>>>(W_hh);
    k_head<<<256, 128>>>(Wp, bp, gamma, beta, out);
}